// round 16
// baseline (speedup 1.0000x reference)
#include <cuda_runtime.h>
#include <cuda_bf16.h>
#include <math.h>

#define CB 4
#define CN 250000
#define CK 32
#define CNB 128            // error bins over e in [0,2]
#define FT 384             // threads in fused kernel (12 warps; >=12 warps to hide LDS chains)
#define NVEC (FT * 2 / 16) // 48 uint4 per bin row in merge
#define PF 12              // prefetch depth
#define NHALF (CN / 2)     // 125000 points per half
#define FUSED_BLOCKS (CB * (CK / 2) * 2)   // b x kpair x half = 128

typedef unsigned long long ull;

// ---------------- static device scratch (no allocations allowed) ----------------
// padded by PF*FT: pipeline prefetch overruns read in-bounds (zero-init) garbage
__device__ float4 g_pack[CB * CN + PF * FT];  // 16 MB

__device__ unsigned g_pall[CB * CK * 2 * CNB];  // partial hist (all), per half
__device__ unsigned g_ppos[CB * CK * 2 * CNB];  // partial hist (pos), per half

// accumulators: zero at module load; re-zeroed by k_lovfin's last block at the
// end of every call so each graph replay starts from zeros.
__device__ int   g_count[CB * CK];
__device__ float g_sum_emb[CB * CK * 3];
__device__ float g_sum_sig[CB * CK * 3];
__device__ float g_sum_sig2[CB * CK];
__device__ float g_seed_bg[CB];
__device__ float g_seed_fg[CB];
__device__ float g_smooth_sum[CB];
__device__ int   g_valid_cnt[CB];
__device__ float g_lov[CB * CK];
__device__ unsigned g_done;

__device__ __forceinline__ float fast_tanh(float x) {
    float r; asm("tanh.approx.f32 %0, %1;" : "=f"(r) : "f"(x)); return r;
}
__device__ __forceinline__ float fast_ex2(float x) {
    float r; asm("ex2.approx.f32 %0, %1;" : "=f"(r) : "f"(x)); return r;
}
// packed f32x2 ops (FFMA2 — only reachable via PTX, per sm_103a quickref)
__device__ __forceinline__ ull fma2(ull a, ull b, ull c) {
    ull d; asm("fma.rn.f32x2 %0, %1, %2, %3;" : "=l"(d) : "l"(a), "l"(b), "l"(c)); return d;
}
__device__ __forceinline__ ull pack2(float lo, float hi) {
    ull d; asm("mov.b64 %0, {%1, %2};" : "=l"(d) : "f"(lo), "f"(hi)); return d;
}
__device__ __forceinline__ void unpack2(ull v, float& lo, float& hi) {
    asm("mov.b64 {%0, %1}, %2;" : "=f"(lo), "=f"(hi) : "l"(v));
}

// ---------------- kernel 1: per-point stats, 2 points/thread, 6 ATOMS/point ----------------
// e-sums exact f32 (3 ATOMS). sigma-sums packed 16-bit lanes, 7-bit values,
// <=512 adds/block: 512*127 = 65024 < 2^16.  (At the ATOMS/LSU floor.)
__device__ __forceinline__ void stats_point(
    float e0, float e1, float e2, float s0, float s1, float s2,
    float sv, int iv, long pbase,
    unsigned* s_cnt, float* s_e, unsigned* s_s01, unsigned* s_s2q, float& bg)
{
    unsigned svq = (unsigned)__float2uint_rn(sv * 65535.f);
    unsigned w = (unsigned)(iv + 1) | (svq << 16);
    g_pack[pbase] = make_float4(e0, e1, e2, __uint_as_float(w));
    if (iv < 0) {
        bg += sv * sv;
    } else {
        int s0q = min(max(__float2int_rn(fmaf(s0, 127.f, 63.5f)), 0), 127);
        int s1q = min(max(__float2int_rn(fmaf(s1, 127.f, 63.5f)), 0), 127);
        int s2q = min(max(__float2int_rn(fmaf(s2, 127.f, 63.5f)), 0), 127);
        int sqq = min(max(__float2int_rn((s0*s0 + s1*s1 + s2*s2) * 1016.f), 0), 127);
        atomicAdd(&s_e[iv * 3 + 0], e0);
        atomicAdd(&s_e[iv * 3 + 1], e1);
        atomicAdd(&s_e[iv * 3 + 2], e2);
        atomicAdd(&s_s01[iv], ((unsigned)s0q << 16) | (unsigned)s1q);
        atomicAdd(&s_s2q[iv], ((unsigned)s2q << 16) | (unsigned)sqq);
        atomicAdd(&s_cnt[iv], 1u);
    }
}

__global__ void k_stats(const float* __restrict__ off,
                        const float* __restrict__ crd,
                        const float* __restrict__ sig,
                        const float* __restrict__ seeds,
                        const int* __restrict__ inst) {
    __shared__ float    s_e[CK * 3];
    __shared__ unsigned s_s01[CK];
    __shared__ unsigned s_s2q[CK];
    __shared__ unsigned s_cnt[CK];
    __shared__ float s_bg;

    int b = blockIdx.y;
    int i = blockIdx.x * blockDim.x + threadIdx.x;
    int n0 = i * 2;

    for (int j = threadIdx.x; j < CK * 3; j += blockDim.x) s_e[j] = 0.f;
    if (threadIdx.x < CK) { s_s01[threadIdx.x] = 0u; s_s2q[threadIdx.x] = 0u; s_cnt[threadIdx.x] = 0u; }
    if (threadIdx.x == 0) s_bg = 0.f;
    __syncthreads();

    float bg = 0.f;
    if (n0 < CN) {                       // CN even: n0+1 valid whenever n0 is
        long pbase = (long)b * CN + n0;
        long vbase = pbase * 3;
        float2 oA = *(const float2*)&off[vbase];
        float2 oB = *(const float2*)&off[vbase + 2];
        float2 oC = *(const float2*)&off[vbase + 4];
        float2 cA = *(const float2*)&crd[vbase];
        float2 cB = *(const float2*)&crd[vbase + 2];
        float2 cC = *(const float2*)&crd[vbase + 4];
        float2 sA = *(const float2*)&sig[vbase];
        float2 sB = *(const float2*)&sig[vbase + 2];
        float2 sC = *(const float2*)&sig[vbase + 4];
        float2 sd = *(const float2*)&seeds[pbase];
        int2   iv = *(const int2*)&inst[pbase];

        float sv0 = fmaf(0.5f, fast_tanh(0.5f * sd.x), 0.5f);
        float sv1 = fmaf(0.5f, fast_tanh(0.5f * sd.y), 0.5f);

        stats_point(fast_tanh(oA.x) + cA.x, fast_tanh(oA.y) + cA.y, fast_tanh(oB.x) + cB.x,
                    sA.x, sA.y, sB.x, sv0, iv.x, pbase, s_cnt, s_e, s_s01, s_s2q, bg);
        stats_point(fast_tanh(oB.y) + cB.y, fast_tanh(oC.x) + cC.x, fast_tanh(oC.y) + cC.y,
                    sB.y, sC.x, sC.y, sv1, iv.y, pbase + 1, s_cnt, s_e, s_s01, s_s2q, bg);
    }
#pragma unroll
    for (int s = 16; s > 0; s >>= 1) bg += __shfl_xor_sync(0xFFFFFFFFu, bg, s);
    if ((threadIdx.x & 31) == 0 && bg != 0.f) atomicAdd(&s_bg, bg);
    __syncthreads();

    if (threadIdx.x < CK) {
        int k = threadIdx.x;
        int bk = b * CK + k;
        unsigned cnt = s_cnt[k];
        if (cnt) {
            float cf = (float)cnt;
            unsigned w01 = s_s01[k], w2q = s_s2q[k];
            float ss0 = ((float)(w01 >> 16)      - 63.5f * cf) * (1.f / 127.f);
            float ss1 = ((float)(w01 & 0xFFFFu)  - 63.5f * cf) * (1.f / 127.f);
            float ss2 = ((float)(w2q >> 16)      - 63.5f * cf) * (1.f / 127.f);
            float ssq =  (float)(w2q & 0xFFFFu) * (1.f / 1016.f);
            atomicAdd(&g_count[bk], (int)cnt);
            atomicAdd(&g_sum_emb[bk * 3 + 0], s_e[k * 3 + 0]);
            atomicAdd(&g_sum_emb[bk * 3 + 1], s_e[k * 3 + 1]);
            atomicAdd(&g_sum_emb[bk * 3 + 2], s_e[k * 3 + 2]);
            atomicAdd(&g_sum_sig[bk * 3 + 0], ss0);
            atomicAdd(&g_sum_sig[bk * 3 + 1], ss1);
            atomicAdd(&g_sum_sig[bk * 3 + 2], ss2);
            atomicAdd(&g_sum_sig2[bk], ssq);
        }
    }
    if (threadIdx.x == 0 && s_bg != 0.f) atomicAdd(&g_seed_bg[b], s_bg);
}

// ---------------- kernel 2: fused dual-class half-N histogram (f32x2 math) ----------------
// Both classes' quadratics evaluated in packed f32x2: 7 FFMA2 replace 12+2 FFMA.
__device__ __forceinline__ void point2(
    float4 v, unsigned tk0, unsigned tk1, int t,
    ull P0p, ull P1p, ull P2p, ull P3p, ull P4p, ull P5p, ull P6p,
    ull CL2E, ull C7,
    unsigned short* __restrict__ h0, unsigned short* __restrict__ h1,
    unsigned* __restrict__ q0h, unsigned* __restrict__ q1h, float& fg)
{
    unsigned w = __float_as_uint(v.w);
    unsigned iv8 = w & 0xFFu;

    ull X = pack2(v.x, v.x);
    ull Y = pack2(v.y, v.y);
    ull Z = pack2(v.z, v.z);
    ull a  = fma2(P0p, X, P3p);
    ull bb = fma2(P1p, Y, P4p);
    ull cc = fma2(P2p, Z, P5p);
    ull t0 = fma2(Z, cc, P6p);
    ull t1 = fma2(Y, bb, t0);
    ull q  = fma2(X, a, t1);
    ull r  = fma2(q, CL2E, C7);     // -q*log2e + 7  (both classes)
    float r0, r1;
    unpack2(r, r0, r1);
    float pj0 = fast_ex2(r0);       // p0 * 128
    float pj1 = fast_ex2(r1);       // p1 * 128

    int j0 = min((int)pj0, CNB - 1);
    int j1 = min((int)pj1, CNB - 1);
    bool l0 = (iv8 == tk0);
    bool l1 = (iv8 == tk1);
    int bin0 = j0 ^ (l0 ? (CNB - 1) : 0);
    int bin1 = j1 ^ (l1 ? (CNB - 1) : 0);
    h0[bin0 * FT + t] = (unsigned short)(h0[bin0 * FT + t] + 1u);
    h1[bin1 * FT + t] = (unsigned short)(h1[bin1 * FT + t] + 1u);
    if (l0) {
        atomicAdd(&q0h[bin0], 1u);
        float sv = (float)(w >> 16) * (1.f / 65535.f);
        float d = sv - pj0 * (1.f / (float)CNB);
        fg += d * d;
    }
    if (l1) {
        atomicAdd(&q1h[bin1], 1u);
        float sv = (float)(w >> 16) * (1.f / 65535.f);
        float d = sv - pj1 * (1.f / (float)CNB);
        fg += d * d;
    }
}

__global__ void __launch_bounds__(FT, 1) k_fused() {
    extern __shared__ char smem[];
    unsigned short* whist0 = (unsigned short*)smem;                 // 96 KB
    unsigned short* whist1 = whist0 + CNB * FT;                     // 96 KB
    unsigned* pos0 = (unsigned*)(smem + 2 * CNB * FT * 2);          // 512 B
    unsigned* pos1 = pos0 + CNB;                                    // 512 B
    __shared__ float s_par[16];

    int idx = blockIdx.x;
    int b = idx >> 5;           // 32 blocks per b (16 kpairs x 2 halves)
    if (b >= CB) return;        // defensive
    int r = idx & 31;
    int kp = r >> 1;
    int half = r & 1;
    int k0 = kp * 2, k1 = kp * 2 + 1;
    int bk0 = b * CK + k0;
    int t = threadIdx.x;

    // thread 0: params for both classes; smooth/valid only from half 0
    if (t == 0) {
#pragma unroll
        for (int cls = 0; cls < 2; cls++) {
            int bk = bk0 + cls;
            int P = g_count[bk];
            float c = fmaxf((float)P, 1.f);
            float c0 = 0.f;
            float dev2 = g_sum_sig2[bk];
#pragma unroll
            for (int d = 0; d < 3; d++) {
                float sume = g_sum_emb[bk * 3 + d];
                float sums = g_sum_sig[bk * 3 + d];
                float ctr = sume / c;
                float sk = sums / c;
                dev2 -= sums * sums / c;
                float se = expf(10.f * sk);
                float sec = se * ctr;
                s_par[cls * 8 + d] = se;
                s_par[cls * 8 + 3 + d] = -2.f * sec;
                c0 += sec * ctr;
            }
            s_par[cls * 8 + 6] = c0;
            if (P > 0 && half == 0) {
                atomicAdd(&g_smooth_sum[b], dev2 / (c * 3.f));
                atomicAdd(&g_valid_cnt[b], 1);
            }
        }
    }

    // zero counters
    {
        uint4* wz = (uint4*)whist0;
        const int NZ = 2 * CNB * FT * 2 / 16;   // 12288
#pragma unroll 4
        for (int i = t; i < NZ; i += FT) wz[i] = make_uint4(0u, 0u, 0u, 0u);
        if (t < 2 * CNB) pos0[t] = 0u;          // pos0+pos1 contiguous
    }
    __syncthreads();

    // packed class-pair params
    ull P0p = pack2(s_par[0], s_par[8]);
    ull P1p = pack2(s_par[1], s_par[9]);
    ull P2p = pack2(s_par[2], s_par[10]);
    ull P3p = pack2(s_par[3], s_par[11]);
    ull P4p = pack2(s_par[4], s_par[12]);
    ull P5p = pack2(s_par[5], s_par[13]);
    ull P6p = pack2(s_par[6], s_par[14]);
    const ull CL2E = pack2(-1.442695040888963f, -1.442695040888963f);
    const ull C7   = pack2(7.0f, 7.0f);

    const float4* base = g_pack + (size_t)b * CN + (size_t)half * NHALF;
    const unsigned tk0 = (unsigned)(k0 + 1), tk1 = (unsigned)(k1 + 1);
    float fg = 0.f;

    const int NFULL = NHALF / FT;           // 325
    const int REM   = NHALF - NFULL * FT;   // 200
    const int NMAIN = (NFULL / PF) * PF;    // 324 (12x software pipeline)

    // 12-deep software pipeline: 12 independent LDG.128 in flight per warp.
    float4 vb[PF];
#pragma unroll
    for (int j = 0; j < PF; j++) vb[j] = base[j * FT + t];

    for (int i = 0; i < NMAIN; i += PF) {
        float4 nb[PF];
#pragma unroll
        for (int j = 0; j < PF; j++) nb[j] = base[(i + PF + j) * FT + t];
#pragma unroll
        for (int j = 0; j < PF; j++)
            point2(vb[j], tk0, tk1, t, P0p, P1p, P2p, P3p, P4p, P5p, P6p,
                   CL2E, C7, whist0, whist1, pos0, pos1, fg);
#pragma unroll
        for (int j = 0; j < PF; j++) vb[j] = nb[j];
    }
    // tail: iters NMAIN..NFULL-1 = 324 -> vb[0]; vb[1] = index 325*FT+t which
    // for t < REM is the remainder point. vb[2..] discarded (pad reads).
    point2(vb[0], tk0, tk1, t, P0p, P1p, P2p, P3p, P4p, P5p, P6p,
           CL2E, C7, whist0, whist1, pos0, pos1, fg);
    if (t < REM)
        point2(vb[1], tk0, tk1, t, P0p, P1p, P2p, P3p, P4p, P5p, P6p,
               CL2E, C7, whist0, whist1, pos0, pos1, fg);

    // warp-reduce seed_fg, leader atomics to global
#pragma unroll
    for (int s = 16; s > 0; s >>= 1) fg += __shfl_xor_sync(0xFFFFFFFFu, fg, s);
    if ((t & 31) == 0 && fg != 0.f) atomicAdd(&g_seed_fg[b], fg);

    __syncthreads();

    // ---- merge per-thread counters, store partial hist (plain STG, disjoint) ----
    if (t < 2 * CNB) {
        int cls = t >> 7;
        int bin = t & (CNB - 1);
        const uint4* row = (const uint4*)((cls ? whist1 : whist0) + bin * FT);
        int start = bin % NVEC;
        unsigned s = 0;
#pragma unroll 8
        for (int c = 0; c < NVEC; c++) {
            int c2 = c + start; if (c2 >= NVEC) c2 -= NVEC;
            uint4 x = row[c2];
            s += (x.x & 0xFFFFu) + (x.x >> 16) + (x.y & 0xFFFFu) + (x.y >> 16)
               + (x.z & 0xFFFFu) + (x.z >> 16) + (x.w & 0xFFFFu) + (x.w >> 16);
        }
        int slot = ((bk0 + cls) * 2 + half) * CNB + bin;
        g_pall[slot] = s;
        g_ppos[slot] = (cls ? pos1 : pos0)[bin];
    }
}

// ---------------- kernel 3: Lovász (warp per bk) + last-block finalize + re-zero ----------------
__global__ void k_lovfin(float* __restrict__ out) {
    __shared__ unsigned s_ticket;
    __shared__ float s_b[CB];
    int bk = blockIdx.x;
    int lane = threadIdx.x;
    int P = g_count[bk];

    float res = 0.f;
    if (P > 0) {
        int binlo = 124 - 4 * lane;          // lane owns bins [binlo..binlo+3] (desc ranks)
        unsigned a4[4] = {0,0,0,0}, p4[4] = {0,0,0,0};
#pragma unroll
        for (int h = 0; h < 2; h++) {
            uint4 xa = *(const uint4*)&g_pall[(bk * 2 + h) * CNB + binlo];
            uint4 xp = *(const uint4*)&g_ppos[(bk * 2 + h) * CNB + binlo];
            a4[0] += xa.x; a4[1] += xa.y; a4[2] += xa.z; a4[3] += xa.w;
            p4[0] += xp.x; p4[1] += xp.y; p4[2] += xp.z; p4[3] += xp.w;
        }
        int la = (int)(a4[0] + a4[1] + a4[2] + a4[3]);
        int lp = (int)(p4[0] + p4[1] + p4[2] + p4[3]);
        int sla = la, slp = lp;
#pragma unroll
        for (int d = 1; d < 32; d <<= 1) {
            int ua = __shfl_up_sync(0xFFFFFFFFu, sla, d);
            int up = __shfl_up_sync(0xFFFFFFFFu, slp, d);
            if (lane >= d) { sla += ua; slp += up; }
        }
        int ca = sla - la, cp = slp - lp;
        float Pd = (float)P, acc = 0.f;
        float Jold = 1.f - (Pd - (float)cp) / (Pd + (float)(ca - cp));
#pragma unroll
        for (int jj = 3; jj >= 0; jj--) {
            if (a4[jj]) {
                ca += (int)a4[jj]; cp += (int)p4[jj];
                float Jnew = 1.f - (Pd - (float)cp) / (Pd + (float)(ca - cp));
                acc += ((float)(binlo + jj) + 0.5f) * (2.f / (float)CNB) * (Jnew - Jold);
                Jold = Jnew;
            }
        }
#pragma unroll
        for (int d = 16; d > 0; d >>= 1) acc += __shfl_down_sync(0xFFFFFFFFu, acc, d);
        res = acc;
    }
    if (lane == 0) g_lov[bk] = res;

    __threadfence();
    if (lane == 0) s_ticket = atomicAdd(&g_done, 1u);
    __syncwarp();
    if (s_ticket != (unsigned)(gridDim.x - 1)) return;

    __threadfence();   // acquire: all g_lov / accumulator stores now visible

    if (lane < CB) {
        float s = 0.f;
#pragma unroll
        for (int k = 0; k < CK; k++) s += g_lov[lane * CK + k];
        s_b[lane] = s;
    }
    __syncwarp();
    if (lane == 0) {
        float loss = 0.f;
#pragma unroll
        for (int b = 0; b < CB; b++) {
            float obj = fmaxf((float)g_valid_cnt[b], 1.f);
            float inst_loss = s_b[b] / obj;
            float smooth_loss = g_smooth_sum[b] / obj;
            float seed_loss = (g_seed_bg[b] + g_seed_fg[b]) / (float)CN;
            loss += inst_loss + 10.f * smooth_loss + 10.f * seed_loss;
        }
        out[0] = loss / (float)CB;
    }

    // re-zero all accumulators for the next call/replay
    for (int i = lane; i < CB * CK; i += 32) {
        g_count[i] = 0; g_sum_sig2[i] = 0.f; g_lov[i] = 0.f;
    }
    for (int i = lane; i < CB * CK * 3; i += 32) {
        g_sum_emb[i] = 0.f; g_sum_sig[i] = 0.f;
    }
    if (lane < CB) {
        g_seed_bg[lane] = 0.f; g_seed_fg[lane] = 0.f;
        g_smooth_sum[lane] = 0.f; g_valid_cnt[lane] = 0;
    }
    if (lane == 0) g_done = 0u;
}

// ---------------- launch ----------------
extern "C" void kernel_launch(void* const* d_in, const int* in_sizes, int n_in,
                              void* d_out, int out_size) {
    const float* off   = (const float*)d_in[0];
    const float* crd   = (const float*)d_in[1];
    const float* sig   = (const float*)d_in[2];
    const float* seeds = (const float*)d_in[3];
    const int*   inst  = (const int*)d_in[4];
    float* out = (float*)d_out;

    const int SMEM_SZ = 2 * CNB * FT * 2 + 2 * CNB * 4;   // 192K + 1K
    cudaFuncSetAttribute(k_fused, cudaFuncAttributeMaxDynamicSharedMemorySize, SMEM_SZ);

    dim3 g1((CN / 2 + 255) / 256, CB);
    k_stats<<<g1, 256>>>(off, crd, sig, seeds, inst);

    k_fused<<<FUSED_BLOCKS, FT, SMEM_SZ>>>();

    k_lovfin<<<CB * CK, 32>>>(out);
}

// round 17
// speedup vs baseline: 1.0634x; 1.0634x over previous
#include <cuda_runtime.h>
#include <cuda_bf16.h>
#include <math.h>

#define CB 4
#define CN 250000
#define CK 32
#define CNB 128            // error bins over e in [0,2]
#define FT 384             // threads in fused kernel (12 warps)
#define NVEC (FT * 2 / 16) // 48 uint4 per bin row in merge
#define PF 8               // prefetch depth
#define NHALF (CN / 2)     // 125000 points per half
#define FUSED_BLOCKS (CB * (CK / 2) * 2)   // b x kpair x half = 128

typedef unsigned long long ull;

// ---------------- static device scratch (no allocations allowed) ----------------
// padded by PF*FT: pipeline prefetch overruns read in-bounds (zero-init) garbage
__device__ float4 g_pack[CB * CN + PF * FT];  // 16 MB

__device__ unsigned g_pall[CB * CK * 2 * CNB];  // partial hist (all), per half
__device__ unsigned g_ppos[CB * CK * 2 * CNB];  // partial hist (pos), per half

// accumulators: zero at module load; re-zeroed by k_lovfin's last block at the
// end of every call so each graph replay starts from zeros.
__device__ int   g_count[CB * CK];
__device__ float g_sum_emb[CB * CK * 3];
__device__ float g_sum_sig[CB * CK * 3];
__device__ float g_sum_sig2[CB * CK];
__device__ float g_seed_bg[CB];
__device__ float g_seed_fg[CB];
__device__ float g_smooth_sum[CB];
__device__ int   g_valid_cnt[CB];
__device__ float g_lov[CB * CK];
__device__ unsigned g_done;

__device__ __forceinline__ float fast_tanh(float x) {
    float r; asm("tanh.approx.f32 %0, %1;" : "=f"(r) : "f"(x)); return r;
}
__device__ __forceinline__ float fast_ex2(float x) {
    float r; asm("ex2.approx.f32 %0, %1;" : "=f"(r) : "f"(x)); return r;
}
__device__ __forceinline__ ull fma2(ull a, ull b, ull c) {
    ull d; asm("fma.rn.f32x2 %0, %1, %2, %3;" : "=l"(d) : "l"(a), "l"(b), "l"(c)); return d;
}
__device__ __forceinline__ ull pack2(float lo, float hi) {
    ull d; asm("mov.b64 %0, {%1, %2};" : "=l"(d) : "f"(lo), "f"(hi)); return d;
}
__device__ __forceinline__ void unpack2(ull v, float& lo, float& hi) {
    asm("mov.b64 {%0, %1}, %2;" : "=f"(lo), "=f"(hi) : "l"(v));
}

// ---------------- kernel 1: per-point stats (unchanged, proven 33us) ----------------
__device__ __forceinline__ void stats_point(
    float e0, float e1, float e2, float s0, float s1, float s2,
    float sv, int iv, long pbase,
    unsigned* s_cnt, float* s_e, unsigned* s_s01, unsigned* s_s2q, float& bg)
{
    unsigned svq = (unsigned)__float2uint_rn(sv * 65535.f);
    unsigned w = (unsigned)(iv + 1) | (svq << 16);
    g_pack[pbase] = make_float4(e0, e1, e2, __uint_as_float(w));
    if (iv < 0) {
        bg += sv * sv;
    } else {
        int s0q = min(max(__float2int_rn(fmaf(s0, 127.f, 63.5f)), 0), 127);
        int s1q = min(max(__float2int_rn(fmaf(s1, 127.f, 63.5f)), 0), 127);
        int s2q = min(max(__float2int_rn(fmaf(s2, 127.f, 63.5f)), 0), 127);
        int sqq = min(max(__float2int_rn((s0*s0 + s1*s1 + s2*s2) * 1016.f), 0), 127);
        atomicAdd(&s_e[iv * 3 + 0], e0);
        atomicAdd(&s_e[iv * 3 + 1], e1);
        atomicAdd(&s_e[iv * 3 + 2], e2);
        atomicAdd(&s_s01[iv], ((unsigned)s0q << 16) | (unsigned)s1q);
        atomicAdd(&s_s2q[iv], ((unsigned)s2q << 16) | (unsigned)sqq);
        atomicAdd(&s_cnt[iv], 1u);
    }
}

__global__ void k_stats(const float* __restrict__ off,
                        const float* __restrict__ crd,
                        const float* __restrict__ sig,
                        const float* __restrict__ seeds,
                        const int* __restrict__ inst) {
    __shared__ float    s_e[CK * 3];
    __shared__ unsigned s_s01[CK];
    __shared__ unsigned s_s2q[CK];
    __shared__ unsigned s_cnt[CK];
    __shared__ float s_bg;

    int b = blockIdx.y;
    int i = blockIdx.x * blockDim.x + threadIdx.x;
    int n0 = i * 2;

    for (int j = threadIdx.x; j < CK * 3; j += blockDim.x) s_e[j] = 0.f;
    if (threadIdx.x < CK) { s_s01[threadIdx.x] = 0u; s_s2q[threadIdx.x] = 0u; s_cnt[threadIdx.x] = 0u; }
    if (threadIdx.x == 0) s_bg = 0.f;
    __syncthreads();

    float bg = 0.f;
    if (n0 < CN) {
        long pbase = (long)b * CN + n0;
        long vbase = pbase * 3;
        float2 oA = *(const float2*)&off[vbase];
        float2 oB = *(const float2*)&off[vbase + 2];
        float2 oC = *(const float2*)&off[vbase + 4];
        float2 cA = *(const float2*)&crd[vbase];
        float2 cB = *(const float2*)&crd[vbase + 2];
        float2 cC = *(const float2*)&crd[vbase + 4];
        float2 sA = *(const float2*)&sig[vbase];
        float2 sB = *(const float2*)&sig[vbase + 2];
        float2 sC = *(const float2*)&sig[vbase + 4];
        float2 sd = *(const float2*)&seeds[pbase];
        int2   iv = *(const int2*)&inst[pbase];

        float sv0 = fmaf(0.5f, fast_tanh(0.5f * sd.x), 0.5f);
        float sv1 = fmaf(0.5f, fast_tanh(0.5f * sd.y), 0.5f);

        stats_point(fast_tanh(oA.x) + cA.x, fast_tanh(oA.y) + cA.y, fast_tanh(oB.x) + cB.x,
                    sA.x, sA.y, sB.x, sv0, iv.x, pbase, s_cnt, s_e, s_s01, s_s2q, bg);
        stats_point(fast_tanh(oB.y) + cB.y, fast_tanh(oC.x) + cC.x, fast_tanh(oC.y) + cC.y,
                    sB.y, sC.x, sC.y, sv1, iv.y, pbase + 1, s_cnt, s_e, s_s01, s_s2q, bg);
    }
#pragma unroll
    for (int s = 16; s > 0; s >>= 1) bg += __shfl_xor_sync(0xFFFFFFFFu, bg, s);
    if ((threadIdx.x & 31) == 0 && bg != 0.f) atomicAdd(&s_bg, bg);
    __syncthreads();

    if (threadIdx.x < CK) {
        int k = threadIdx.x;
        int bk = b * CK + k;
        unsigned cnt = s_cnt[k];
        if (cnt) {
            float cf = (float)cnt;
            unsigned w01 = s_s01[k], w2q = s_s2q[k];
            float ss0 = ((float)(w01 >> 16)      - 63.5f * cf) * (1.f / 127.f);
            float ss1 = ((float)(w01 & 0xFFFFu)  - 63.5f * cf) * (1.f / 127.f);
            float ss2 = ((float)(w2q >> 16)      - 63.5f * cf) * (1.f / 127.f);
            float ssq =  (float)(w2q & 0xFFFFu) * (1.f / 1016.f);
            atomicAdd(&g_count[bk], (int)cnt);
            atomicAdd(&g_sum_emb[bk * 3 + 0], s_e[k * 3 + 0]);
            atomicAdd(&g_sum_emb[bk * 3 + 1], s_e[k * 3 + 1]);
            atomicAdd(&g_sum_emb[bk * 3 + 2], s_e[k * 3 + 2]);
            atomicAdd(&g_sum_sig[bk * 3 + 0], ss0);
            atomicAdd(&g_sum_sig[bk * 3 + 1], ss1);
            atomicAdd(&g_sum_sig[bk * 3 + 2], ss2);
            atomicAdd(&g_sum_sig2[bk], ssq);
        }
    }
    if (threadIdx.x == 0 && s_bg != 0.f) atomicAdd(&g_seed_bg[b], s_bg);
}

// ---------------- fused kernel helpers ----------------
// Compute both classes' bins + p*128 for one point (f32x2 math).
__device__ __forceinline__ void eval_point(
    float4 v,
    ull P0p, ull P1p, ull P2p, ull P3p, ull P4p, ull P5p, ull P6p,
    ull CL2E, ull C7, unsigned tk0, unsigned tk1,
    int& bin0, int& bin1, float& pj0, float& pj1,
    bool& l0, bool& l1, unsigned& w)
{
    w = __float_as_uint(v.w);
    unsigned iv8 = w & 0xFFu;
    ull X = pack2(v.x, v.x);
    ull Y = pack2(v.y, v.y);
    ull Z = pack2(v.z, v.z);
    ull a  = fma2(P0p, X, P3p);
    ull bb = fma2(P1p, Y, P4p);
    ull cc = fma2(P2p, Z, P5p);
    ull t0 = fma2(Z, cc, P6p);
    ull t1 = fma2(Y, bb, t0);
    ull q  = fma2(X, a, t1);
    ull r  = fma2(q, CL2E, C7);
    float r0, r1;
    unpack2(r, r0, r1);
    pj0 = fast_ex2(r0);
    pj1 = fast_ex2(r1);
    int j0 = min((int)pj0, CNB - 1);
    int j1 = min((int)pj1, CNB - 1);
    l0 = (iv8 == tk0);
    l1 = (iv8 == tk1);
    bin0 = j0 ^ (l0 ? (CNB - 1) : 0);
    bin1 = j1 ^ (l1 ? (CNB - 1) : 0);
}

__device__ __forceinline__ void rare_pos(
    bool l, unsigned w, float pj, int bin, unsigned* qh, float& fg)
{
    if (l) {
        atomicAdd(&qh[bin], 1u);
        float sv = (float)(w >> 16) * (1.f / 65535.f);
        float d = sv - pj * (1.f / (float)CNB);
        fg += d * d;
    }
}

// Batched RMW for TWO points: all 4 LDS issue before any STS (breaks the
// ptxas alias-serialized LDS->STS chain). Same-bin collisions within the
// batch handled exactly: both loads see the old value; store +2 once.
__device__ __forceinline__ void pair2(
    float4 vA, float4 vB, unsigned tk0, unsigned tk1, int t,
    ull P0p, ull P1p, ull P2p, ull P3p, ull P4p, ull P5p, ull P6p,
    ull CL2E, ull C7,
    unsigned short* __restrict__ h0, unsigned short* __restrict__ h1,
    unsigned* __restrict__ q0h, unsigned* __restrict__ q1h, float& fg)
{
    int bA0, bA1, bB0, bB1; float pA0, pA1, pB0, pB1;
    bool lA0, lA1, lB0, lB1; unsigned wA, wB;
    eval_point(vA, P0p, P1p, P2p, P3p, P4p, P5p, P6p, CL2E, C7, tk0, tk1,
               bA0, bA1, pA0, pA1, lA0, lA1, wA);
    eval_point(vB, P0p, P1p, P2p, P3p, P4p, P5p, P6p, CL2E, C7, tk0, tk1,
               bB0, bB1, pB0, pB1, lB0, lB1, wB);

    // all 4 loads first (pipelined; no intervening stores)
    unsigned short uA0 = h0[bA0 * FT + t];
    unsigned short uB0 = h0[bB0 * FT + t];
    unsigned short uA1 = h1[bA1 * FT + t];
    unsigned short uB1 = h1[bB1 * FT + t];
    bool e0 = (bA0 == bB0);
    bool e1 = (bA1 == bB1);
    h0[bA0 * FT + t] = (unsigned short)(uA0 + 1u + (e0 ? 1u : 0u));
    if (!e0) h0[bB0 * FT + t] = (unsigned short)(uB0 + 1u);
    h1[bA1 * FT + t] = (unsigned short)(uA1 + 1u + (e1 ? 1u : 0u));
    if (!e1) h1[bB1 * FT + t] = (unsigned short)(uB1 + 1u);

    rare_pos(lA0, wA, pA0, bA0, q0h, fg);
    rare_pos(lA1, wA, pA1, bA1, q1h, fg);
    rare_pos(lB0, wB, pB0, bB0, q0h, fg);
    rare_pos(lB1, wB, pB1, bB1, q1h, fg);
}

// single-point path for tail
__device__ __forceinline__ void point2(
    float4 v, unsigned tk0, unsigned tk1, int t,
    ull P0p, ull P1p, ull P2p, ull P3p, ull P4p, ull P5p, ull P6p,
    ull CL2E, ull C7,
    unsigned short* __restrict__ h0, unsigned short* __restrict__ h1,
    unsigned* __restrict__ q0h, unsigned* __restrict__ q1h, float& fg)
{
    int b0, b1; float p0, p1; bool l0, l1; unsigned w;
    eval_point(v, P0p, P1p, P2p, P3p, P4p, P5p, P6p, CL2E, C7, tk0, tk1,
               b0, b1, p0, p1, l0, l1, w);
    unsigned short u0 = h0[b0 * FT + t];
    unsigned short u1 = h1[b1 * FT + t];
    h0[b0 * FT + t] = (unsigned short)(u0 + 1u);
    h1[b1 * FT + t] = (unsigned short)(u1 + 1u);
    rare_pos(l0, w, p0, b0, q0h, fg);
    rare_pos(l1, w, p1, b1, q1h, fg);
}

// ---------------- kernel 2: fused dual-class half-N histogram ----------------
__global__ void __launch_bounds__(FT, 1) k_fused() {
    extern __shared__ char smem[];
    unsigned short* whist0 = (unsigned short*)smem;                 // 96 KB
    unsigned short* whist1 = whist0 + CNB * FT;                     // 96 KB
    unsigned* pos0 = (unsigned*)(smem + 2 * CNB * FT * 2);          // 512 B
    unsigned* pos1 = pos0 + CNB;                                    // 512 B
    __shared__ float s_par[16];

    int idx = blockIdx.x;
    int b = idx >> 5;
    if (b >= CB) return;
    int r = idx & 31;
    int kp = r >> 1;
    int half = r & 1;
    int k0 = kp * 2, k1 = kp * 2 + 1;
    int bk0 = b * CK + k0;
    int t = threadIdx.x;

    if (t == 0) {
#pragma unroll
        for (int cls = 0; cls < 2; cls++) {
            int bk = bk0 + cls;
            int P = g_count[bk];
            float c = fmaxf((float)P, 1.f);
            float c0 = 0.f;
            float dev2 = g_sum_sig2[bk];
#pragma unroll
            for (int d = 0; d < 3; d++) {
                float sume = g_sum_emb[bk * 3 + d];
                float sums = g_sum_sig[bk * 3 + d];
                float ctr = sume / c;
                float sk = sums / c;
                dev2 -= sums * sums / c;
                float se = expf(10.f * sk);
                float sec = se * ctr;
                s_par[cls * 8 + d] = se;
                s_par[cls * 8 + 3 + d] = -2.f * sec;
                c0 += sec * ctr;
            }
            s_par[cls * 8 + 6] = c0;
            if (P > 0 && half == 0) {
                atomicAdd(&g_smooth_sum[b], dev2 / (c * 3.f));
                atomicAdd(&g_valid_cnt[b], 1);
            }
        }
    }

    {
        uint4* wz = (uint4*)whist0;
        const int NZ = 2 * CNB * FT * 2 / 16;
#pragma unroll 4
        for (int i = t; i < NZ; i += FT) wz[i] = make_uint4(0u, 0u, 0u, 0u);
        if (t < 2 * CNB) pos0[t] = 0u;
    }
    __syncthreads();

    ull P0p = pack2(s_par[0], s_par[8]);
    ull P1p = pack2(s_par[1], s_par[9]);
    ull P2p = pack2(s_par[2], s_par[10]);
    ull P3p = pack2(s_par[3], s_par[11]);
    ull P4p = pack2(s_par[4], s_par[12]);
    ull P5p = pack2(s_par[5], s_par[13]);
    ull P6p = pack2(s_par[6], s_par[14]);
    const ull CL2E = pack2(-1.442695040888963f, -1.442695040888963f);
    const ull C7   = pack2(7.0f, 7.0f);

    const float4* base = g_pack + (size_t)b * CN + (size_t)half * NHALF;
    const unsigned tk0 = (unsigned)(k0 + 1), tk1 = (unsigned)(k1 + 1);
    float fg = 0.f;

    const int NFULL = NHALF / FT;           // 325
    const int REM   = NHALF - NFULL * FT;   // 200
    const int NMAIN = (NFULL / PF) * PF;    // 320

    float4 vb[PF];
#pragma unroll
    for (int j = 0; j < PF; j++) vb[j] = base[j * FT + t];

    for (int i = 0; i < NMAIN; i += PF) {
        float4 nb[PF];
#pragma unroll
        for (int j = 0; j < PF; j++) nb[j] = base[(i + PF + j) * FT + t];
#pragma unroll
        for (int j = 0; j < PF; j += 2)
            pair2(vb[j], vb[j + 1], tk0, tk1, t,
                  P0p, P1p, P2p, P3p, P4p, P5p, P6p, CL2E, C7,
                  whist0, whist1, pos0, pos1, fg);
#pragma unroll
        for (int j = 0; j < PF; j++) vb[j] = nb[j];
    }
    // tail: iters 320..324 in vb[0..4]; vb[5] = 325*FT+t = remainder for t < REM
    pair2(vb[0], vb[1], tk0, tk1, t, P0p, P1p, P2p, P3p, P4p, P5p, P6p,
          CL2E, C7, whist0, whist1, pos0, pos1, fg);
    pair2(vb[2], vb[3], tk0, tk1, t, P0p, P1p, P2p, P3p, P4p, P5p, P6p,
          CL2E, C7, whist0, whist1, pos0, pos1, fg);
    point2(vb[4], tk0, tk1, t, P0p, P1p, P2p, P3p, P4p, P5p, P6p,
           CL2E, C7, whist0, whist1, pos0, pos1, fg);
    if (t < REM)
        point2(vb[5], tk0, tk1, t, P0p, P1p, P2p, P3p, P4p, P5p, P6p,
               CL2E, C7, whist0, whist1, pos0, pos1, fg);

#pragma unroll
    for (int s = 16; s > 0; s >>= 1) fg += __shfl_xor_sync(0xFFFFFFFFu, fg, s);
    if ((t & 31) == 0 && fg != 0.f) atomicAdd(&g_seed_fg[b], fg);

    __syncthreads();

    if (t < 2 * CNB) {
        int cls = t >> 7;
        int bin = t & (CNB - 1);
        const uint4* row = (const uint4*)((cls ? whist1 : whist0) + bin * FT);
        int start = bin % NVEC;
        unsigned s = 0;
#pragma unroll 8
        for (int c = 0; c < NVEC; c++) {
            int c2 = c + start; if (c2 >= NVEC) c2 -= NVEC;
            uint4 x = row[c2];
            s += (x.x & 0xFFFFu) + (x.x >> 16) + (x.y & 0xFFFFu) + (x.y >> 16)
               + (x.z & 0xFFFFu) + (x.z >> 16) + (x.w & 0xFFFFu) + (x.w >> 16);
        }
        int slot = ((bk0 + cls) * 2 + half) * CNB + bin;
        g_pall[slot] = s;
        g_ppos[slot] = (cls ? pos1 : pos0)[bin];
    }
}

// ---------------- kernel 3: Lovász (warp per bk) + last-block finalize + re-zero ----------------
__global__ void k_lovfin(float* __restrict__ out) {
    __shared__ unsigned s_ticket;
    __shared__ float s_b[CB];
    int bk = blockIdx.x;
    int lane = threadIdx.x;
    int P = g_count[bk];

    float res = 0.f;
    if (P > 0) {
        int binlo = 124 - 4 * lane;
        unsigned a4[4] = {0,0,0,0}, p4[4] = {0,0,0,0};
#pragma unroll
        for (int h = 0; h < 2; h++) {
            uint4 xa = *(const uint4*)&g_pall[(bk * 2 + h) * CNB + binlo];
            uint4 xp = *(const uint4*)&g_ppos[(bk * 2 + h) * CNB + binlo];
            a4[0] += xa.x; a4[1] += xa.y; a4[2] += xa.z; a4[3] += xa.w;
            p4[0] += xp.x; p4[1] += xp.y; p4[2] += xp.z; p4[3] += xp.w;
        }
        int la = (int)(a4[0] + a4[1] + a4[2] + a4[3]);
        int lp = (int)(p4[0] + p4[1] + p4[2] + p4[3]);
        int sla = la, slp = lp;
#pragma unroll
        for (int d = 1; d < 32; d <<= 1) {
            int ua = __shfl_up_sync(0xFFFFFFFFu, sla, d);
            int up = __shfl_up_sync(0xFFFFFFFFu, slp, d);
            if (lane >= d) { sla += ua; slp += up; }
        }
        int ca = sla - la, cp = slp - lp;
        float Pd = (float)P, acc = 0.f;
        float Jold = 1.f - (Pd - (float)cp) / (Pd + (float)(ca - cp));
#pragma unroll
        for (int jj = 3; jj >= 0; jj--) {
            if (a4[jj]) {
                ca += (int)a4[jj]; cp += (int)p4[jj];
                float Jnew = 1.f - (Pd - (float)cp) / (Pd + (float)(ca - cp));
                acc += ((float)(binlo + jj) + 0.5f) * (2.f / (float)CNB) * (Jnew - Jold);
                Jold = Jnew;
            }
        }
#pragma unroll
        for (int d = 16; d > 0; d >>= 1) acc += __shfl_down_sync(0xFFFFFFFFu, acc, d);
        res = acc;
    }
    if (lane == 0) g_lov[bk] = res;

    __threadfence();
    if (lane == 0) s_ticket = atomicAdd(&g_done, 1u);
    __syncwarp();
    if (s_ticket != (unsigned)(gridDim.x - 1)) return;

    __threadfence();

    if (lane < CB) {
        float s = 0.f;
#pragma unroll
        for (int k = 0; k < CK; k++) s += g_lov[lane * CK + k];
        s_b[lane] = s;
    }
    __syncwarp();
    if (lane == 0) {
        float loss = 0.f;
#pragma unroll
        for (int b = 0; b < CB; b++) {
            float obj = fmaxf((float)g_valid_cnt[b], 1.f);
            float inst_loss = s_b[b] / obj;
            float smooth_loss = g_smooth_sum[b] / obj;
            float seed_loss = (g_seed_bg[b] + g_seed_fg[b]) / (float)CN;
            loss += inst_loss + 10.f * smooth_loss + 10.f * seed_loss;
        }
        out[0] = loss / (float)CB;
    }

    for (int i = lane; i < CB * CK; i += 32) {
        g_count[i] = 0; g_sum_sig2[i] = 0.f; g_lov[i] = 0.f;
    }
    for (int i = lane; i < CB * CK * 3; i += 32) {
        g_sum_emb[i] = 0.f; g_sum_sig[i] = 0.f;
    }
    if (lane < CB) {
        g_seed_bg[lane] = 0.f; g_seed_fg[lane] = 0.f;
        g_smooth_sum[lane] = 0.f; g_valid_cnt[lane] = 0;
    }
    if (lane == 0) g_done = 0u;
}

// ---------------- launch ----------------
extern "C" void kernel_launch(void* const* d_in, const int* in_sizes, int n_in,
                              void* d_out, int out_size) {
    const float* off   = (const float*)d_in[0];
    const float* crd   = (const float*)d_in[1];
    const float* sig   = (const float*)d_in[2];
    const float* seeds = (const float*)d_in[3];
    const int*   inst  = (const int*)d_in[4];
    float* out = (float*)d_out;

    const int SMEM_SZ = 2 * CNB * FT * 2 + 2 * CNB * 4;   // 192K + 1K
    cudaFuncSetAttribute(k_fused, cudaFuncAttributeMaxDynamicSharedMemorySize, SMEM_SZ);

    dim3 g1((CN / 2 + 255) / 256, CB);
    k_stats<<<g1, 256>>>(off, crd, sig, seeds, inst);

    k_fused<<<FUSED_BLOCKS, FT, SMEM_SZ>>>();

    k_lovfin<<<CB * CK, 32>>>(out);
}